// round 1
// baseline (speedup 1.0000x reference)
#include <cuda_runtime.h>
#include <math.h>

#define NPTS 8192
#define DIM  256
#define KNN  11          // k+1
#define TM   64
#define TN   128
#define KB   32
#define NTHREADS 256
#define NROWB (NPTS / TM)    // 128 CTAs
#define NCOLT (NPTS / TN)    // 64 column tiles
#define NCHUNK (DIM / KB)    // 8 k-chunks
#define BIGF 1e30f

// ---- device scratch (no allocations allowed) ----
__device__ float g_sq[NPTS];
__device__ float g_colpart[NROWB * DIM];
__device__ float g_disc[NROWB];

typedef unsigned long long u64;

__device__ __forceinline__ u64 pack2(float lo, float hi) {
    u64 r;
    asm("mov.b64 %0, {%1, %2};" : "=l"(r) : "f"(lo), "f"(hi));
    return r;
}
__device__ __forceinline__ void unpack2(u64 v, float& lo, float& hi) {
    asm("mov.b64 {%0, %1}, %2;" : "=f"(lo), "=f"(hi) : "l"(v));
}
// packed dual-FMA (Blackwell f32x2 pipe): d = a*b + d  on two lanes
__device__ __forceinline__ void ffma2(u64& d, u64 a, u64 b) {
    asm("fma.rn.f32x2 %0, %1, %2, %0;" : "+l"(d) : "l"(a), "l"(b));
}

// FFMA-pipe-only sqrt (avoids MUFU bottleneck): rel err ~5e-6
__device__ __forceinline__ float fast_sqrt(float x) {
    if (x < 1e-12f) return 0.f;
    float xh = 0.5f * x;
    int i = __float_as_int(x);
    i = 0x5f3759df - (i >> 1);
    float y = __int_as_float(i);
    y = y * (1.5f - xh * y * y);
    y = y * (1.5f - xh * y * y);
    return x * y;
}

// serialized top-11 insert; rowmax is monotone-decreasing so the lock-free
// pre-check outside is safe (stale reads are only ever too large).
__device__ __forceinline__ void topk_insert(float* heap, float* rowmax, int* locks,
                                            int r, float d) {
    volatile float* vheap = heap;
    volatile float* vmax  = rowmax;
    while (atomicCAS(&locks[r], 0, 1) != 0) { }
    __threadfence_block();
    if (d < vmax[r]) {
        int mi = 0; float mx = vheap[r * 12 + 0];
        #pragma unroll
        for (int t = 1; t < KNN; t++) {
            float v = vheap[r * 12 + t];
            if (v > mx) { mx = v; mi = t; }
        }
        vheap[r * 12 + mi] = d;
        float nmx = vheap[r * 12 + 0];
        #pragma unroll
        for (int t = 1; t < KNN; t++) {
            float v = vheap[r * 12 + t];
            nmx = fmaxf(nmx, v);
        }
        vmax[r] = nmx;
    }
    __threadfence_block();
    atomicExch(&locks[r], 0);
}

// ---- squared norms of target rows: one warp per row ----
__global__ void tg_sq_kernel(const float* __restrict__ x) {
    int warp = (blockIdx.x * blockDim.x + threadIdx.x) >> 5;
    int lane = threadIdx.x & 31;
    const float* row = x + (size_t)warp * DIM;
    float s = 0.f;
    #pragma unroll
    for (int i = 0; i < DIM / 32; i++) {
        float v = row[lane + i * 32];
        s = fmaf(v, v, s);
    }
    #pragma unroll
    for (int o = 16; o; o >>= 1) s += __shfl_xor_sync(0xffffffffu, s, o);
    if (lane == 0) g_sq[warp] = s;
}

// ---- column-sum differences for GDDM (deterministic two-stage) ----
__global__ void tg_coldiff_kernel(const float* __restrict__ src,
                                  const float* __restrict__ tgt) {
    int d = threadIdx.x;        // 256 = DIM
    int b = blockIdx.x;         // 128 blocks x 64 rows
    int r0 = b * (NPTS / NROWB);
    float s = 0.f;
    for (int r = 0; r < NPTS / NROWB; r++) {
        size_t idx = (size_t)(r0 + r) * DIM + d;
        s += src[idx] - tgt[idx];
    }
    g_colpart[b * DIM + d] = s;
}

// ---- fused cdist + row-sum + top-11 + TSDM head ----
__global__ void __launch_bounds__(NTHREADS, 1)
tg_main_kernel(const float* __restrict__ X,
               const float* __restrict__ w_tsdm,
               const float* __restrict__ b_tsdm)
{
    extern __shared__ float smem[];
    float* As     = smem;                       // [DIM][TM] = 16384 f
    float* Bs     = As + DIM * TM;              // [2][KB][TN] = 8192 f
    float* sqA    = Bs + 2 * KB * TN;           // TM
    float* sqC    = sqA + TM;                   // TN
    float* heap   = sqC + TN;                   // TM * 12 (11 + pad)
    float* rowmax = heap + TM * 12;             // TM
    float* red    = rowmax + TM;                // TM * 16
    int*   locks  = (int*)(red + TM * 16);      // TM

    const int tid = threadIdx.x;
    const int tr  = tid >> 4;     // 0..15 -> rows tr*4..tr*4+3
    const int tc  = tid & 15;     // 0..15 -> cols tc*8..tc*8+7
    const int rowbase = blockIdx.x * TM;

    for (int i = tid; i < TM * 12; i += NTHREADS) heap[i] = BIGF;
    if (tid < TM) {
        rowmax[tid] = BIGF;
        locks[tid]  = 0;
        sqA[tid]    = g_sq[rowbase + tid];
    }

    // preload A tile transposed into smem: As[k][r]
    #pragma unroll
    for (int i = 0; i < 16; i++) {
        int li = tid + i * NTHREADS;        // 0..4095 over (r, kq)
        int r  = li >> 6;
        int kq = li & 63;
        float4 v = *(const float4*)(X + (size_t)(rowbase + r) * DIM + kq * 4);
        int k0 = kq * 4;
        As[(k0 + 0) * TM + r] = v.x;
        As[(k0 + 1) * TM + r] = v.y;
        As[(k0 + 2) * TM + r] = v.z;
        As[(k0 + 3) * TM + r] = v.w;
    }
    __syncthreads();

    const int bj  = tid >> 1;           // 0..127: B row (= column index)
    const int bk4 = (tid & 1) * 4;      // float4 slot base within k-chunk

    float rsum[4] = {0.f, 0.f, 0.f, 0.f};

    for (int ct = 0; ct < NCOLT; ct++) {
        const int colbase = ct * TN;
        __syncthreads();   // previous epilogue done before overwriting sqC/Bs
        if (tid < TN) sqC[tid] = g_sq[colbase + tid];

        const float* Bbase = X + (size_t)colbase * DIM;

        // chunk 0 -> buffer 0
        float4 breg[4];
        #pragma unroll
        for (int i = 0; i < 4; i++)
            breg[i] = *(const float4*)(Bbase + bj * DIM + (bk4 + i) * 4);
        #pragma unroll
        for (int i = 0; i < 4; i++) {
            int k0 = (bk4 + i) * 4;
            Bs[(k0 + 0) * TN + bj] = breg[i].x;
            Bs[(k0 + 1) * TN + bj] = breg[i].y;
            Bs[(k0 + 2) * TN + bj] = breg[i].z;
            Bs[(k0 + 3) * TN + bj] = breg[i].w;
        }
        __syncthreads();

        u64 acc[4][4];
        #pragma unroll
        for (int i = 0; i < 4; i++)
            #pragma unroll
            for (int j = 0; j < 4; j++) acc[i][j] = 0ull;

        for (int kc = 0; kc < NCHUNK; kc++) {
            if (kc + 1 < NCHUNK) {     // prefetch next chunk into regs
                #pragma unroll
                for (int i = 0; i < 4; i++)
                    breg[i] = *(const float4*)(Bbase + bj * DIM +
                                               (kc + 1) * KB + (bk4 + i) * 4);
            }
            const float* Asb = As + kc * KB * TM;
            const float* Bsb = Bs + (kc & 1) * KB * TN;
            #pragma unroll 8
            for (int k = 0; k < KB; k++) {
                float4 av = *(const float4*)(Asb + k * TM + tr * 4);
                float4 b0 = *(const float4*)(Bsb + k * TN + tc * 8);
                float4 b1 = *(const float4*)(Bsb + k * TN + tc * 8 + 4);
                u64 ap0 = pack2(av.x, av.x), ap1 = pack2(av.y, av.y);
                u64 ap2 = pack2(av.z, av.z), ap3 = pack2(av.w, av.w);
                u64 bp0 = pack2(b0.x, b0.y), bp1 = pack2(b0.z, b0.w);
                u64 bp2 = pack2(b1.x, b1.y), bp3 = pack2(b1.z, b1.w);
                ffma2(acc[0][0], ap0, bp0); ffma2(acc[0][1], ap0, bp1);
                ffma2(acc[0][2], ap0, bp2); ffma2(acc[0][3], ap0, bp3);
                ffma2(acc[1][0], ap1, bp0); ffma2(acc[1][1], ap1, bp1);
                ffma2(acc[1][2], ap1, bp2); ffma2(acc[1][3], ap1, bp3);
                ffma2(acc[2][0], ap2, bp0); ffma2(acc[2][1], ap2, bp1);
                ffma2(acc[2][2], ap2, bp2); ffma2(acc[2][3], ap2, bp3);
                ffma2(acc[3][0], ap3, bp0); ffma2(acc[3][1], ap3, bp1);
                ffma2(acc[3][2], ap3, bp2); ffma2(acc[3][3], ap3, bp3);
            }
            __syncthreads();
            if (kc + 1 < NCHUNK) {     // regs -> other buffer
                float* Bsn = Bs + ((kc + 1) & 1) * KB * TN;
                #pragma unroll
                for (int i = 0; i < 4; i++) {
                    int k0 = (bk4 + i) * 4;
                    Bsn[(k0 + 0) * TN + bj] = breg[i].x;
                    Bsn[(k0 + 1) * TN + bj] = breg[i].y;
                    Bsn[(k0 + 2) * TN + bj] = breg[i].z;
                    Bsn[(k0 + 3) * TN + bj] = breg[i].w;
                }
                __syncthreads();
            }
        }

        // epilogue: d2 -> dist -> row sums + top-11
        #pragma unroll
        for (int i = 0; i < 4; i++) {
            int r = tr * 4 + i;
            float sa = sqA[r];
            float rs = 0.f;
            #pragma unroll
            for (int j = 0; j < 4; j++) {
                float lo, hi; unpack2(acc[i][j], lo, hi);
                int c0 = tc * 8 + j * 2;
                float d2a = fmaxf(sa + sqC[c0]     - 2.f * lo, 0.f);
                float d2b = fmaxf(sa + sqC[c0 + 1] - 2.f * hi, 0.f);
                float da = fast_sqrt(d2a);
                float db = fast_sqrt(d2b);
                rs += da + db;
                if (da < ((volatile float*)rowmax)[r])
                    topk_insert(heap, rowmax, locks, r, da);
                if (db < ((volatile float*)rowmax)[r])
                    topk_insert(heap, rowmax, locks, r, db);
            }
            rsum[i] += rs;
        }
    }

    // deterministic cross-thread row-sum reduction
    __syncthreads();
    #pragma unroll
    for (int i = 0; i < 4; i++) red[(tr * 4 + i) * 16 + tc] = rsum[i];
    __syncthreads();
    if (tid < TM) {
        float s = 0.f;
        #pragma unroll
        for (int t = 0; t < 16; t++) s += red[tid * 16 + t];
        float sep = s * (1.f / (float)(NPTS - 1));
        float hs = 0.f, hmin = BIGF;
        #pragma unroll
        for (int t = 0; t < KNN; t++) {
            float v = heap[tid * 12 + t];
            hs += v;
            hmin = fminf(hmin, v);
        }
        float comp = (hs - hmin) * 0.1f;  // drop self-distance, mean of 10
        float disc = fabsf(comp * w_tsdm[0] + sep * w_tsdm[1] + b_tsdm[0]);
        rowmax[tid] = disc;               // rowmax reused as scratch
    }
    __syncthreads();
    if (tid == 0) {
        float s = 0.f;
        for (int r = 0; r < TM; r++) s += rowmax[r];
        g_disc[blockIdx.x] = s;
    }
}

// ---- final: GDDM head + disc mean, fixed-order sums ----
__global__ void tg_final_kernel(const float* __restrict__ w_gddm,
                                const float* __restrict__ b_gddm,
                                float* __restrict__ out)
{
    __shared__ float buf[DIM];
    int d = threadIdx.x;
    float s = 0.f;
    for (int b = 0; b < NROWB; b++) s += g_colpart[b * DIM + d];
    buf[d] = (s * (1.f / (float)NPTS)) * w_gddm[d];
    __syncthreads();
    if (d == 0) {
        float t = 0.f;
        for (int i = 0; i < DIM; i++) t += buf[i];
        out[0] = fabsf(t + b_gddm[0]);        // loss_gdd
        float ds = 0.f;
        for (int i = 0; i < NROWB; i++) ds += g_disc[i];
        out[1] = ds * (1.f / (float)NPTS);    // disc_loss
    }
}

extern "C" void kernel_launch(void* const* d_in, const int* in_sizes, int n_in,
                              void* d_out, int out_size) {
    const float* src    = (const float*)d_in[0];
    const float* tgt    = (const float*)d_in[1];
    const float* w_tsdm = (const float*)d_in[2];
    const float* b_tsdm = (const float*)d_in[3];
    const float* w_gddm = (const float*)d_in[4];
    const float* b_gddm = (const float*)d_in[5];
    float* out = (float*)d_out;

    size_t smem_bytes = (size_t)(DIM * TM + 2 * KB * TN + TM + TN +
                                 TM * 12 + TM + TM * 16 + TM) * sizeof(float);
    cudaFuncSetAttribute(tg_main_kernel,
                         cudaFuncAttributeMaxDynamicSharedMemorySize,
                         (int)smem_bytes);

    tg_sq_kernel<<<NPTS / 8, 256>>>(tgt);
    tg_coldiff_kernel<<<NROWB, DIM>>>(src, tgt);
    tg_main_kernel<<<NROWB, NTHREADS, smem_bytes>>>(tgt, w_tsdm, b_tsdm);
    tg_final_kernel<<<1, DIM>>>(w_gddm, b_gddm, out);
}

// round 3
// speedup vs baseline: 1.5541x; 1.5541x over previous
#include <cuda_runtime.h>
#include <math.h>

#define NPTS 8192
#define DIM  256
#define KNN  11            // k+1
#define TM   128           // rows per CTA
#define TN   128           // cols per tile iter
#define HALF 4096          // cols per CTA (2 halves)
#define NCT  (HALF / TN)   // 32 col tiles per CTA
#define KB   16
#define NKC  (DIM / KB)    // 16 k-chunks
#define NTHREADS 512
#define PITCH_A 132
#define BIGF 1e30f

// ---- device scratch ----
__device__ float g_sq[NPTS];
__device__ float g_colpart[128 * DIM];
__device__ float g_psum[2 * NPTS];
__device__ float g_ptopk[2 * NPTS * 12];
__device__ float g_disc[32];

typedef unsigned long long u64;

__device__ __forceinline__ u64 pack2(float lo, float hi) {
    u64 r;
    asm("mov.b64 %0, {%1, %2};" : "=l"(r) : "f"(lo), "f"(hi));
    return r;
}
__device__ __forceinline__ void unpack2(u64 v, float& lo, float& hi) {
    asm("mov.b64 {%0, %1}, %2;" : "=f"(lo), "=f"(hi) : "l"(v));
}
__device__ __forceinline__ void ffma2(u64& d, u64 a, u64 b) {
    asm("fma.rn.f32x2 %0, %1, %2, %0;" : "+l"(d) : "l"(a), "l"(b));
}

__device__ __forceinline__ void topk_insert(float* heap, float* rowmax, int* locks,
                                            int r, float d) {
    volatile float* vheap = heap;
    volatile float* vmax  = rowmax;
    while (atomicCAS(&locks[r], 0, 1) != 0) { }
    __threadfence_block();
    if (d < vmax[r]) {
        int mi = 0; float mx = vheap[r * 12 + 0];
        #pragma unroll
        for (int t = 1; t < KNN; t++) {
            float v = vheap[r * 12 + t];
            if (v > mx) { mx = v; mi = t; }
        }
        vheap[r * 12 + mi] = d;
        float nmx = vheap[r * 12 + 0];
        #pragma unroll
        for (int t = 1; t < KNN; t++) nmx = fmaxf(nmx, vheap[r * 12 + t]);
        vmax[r] = nmx;
    }
    __threadfence_block();
    atomicExch(&locks[r], 0);
}

// ---- squared norms: one warp per row ----
__global__ void tg_sq_kernel(const float* __restrict__ x) {
    int warp = (blockIdx.x * blockDim.x + threadIdx.x) >> 5;
    int lane = threadIdx.x & 31;
    const float* row = x + (size_t)warp * DIM;
    float s = 0.f;
    #pragma unroll
    for (int i = 0; i < DIM / 32; i++) {
        float v = row[lane + i * 32];
        s = fmaf(v, v, s);
    }
    #pragma unroll
    for (int o = 16; o; o >>= 1) s += __shfl_xor_sync(0xffffffffu, s, o);
    if (lane == 0) g_sq[warp] = s;
}

// ---- column-sum differences for GDDM ----
__global__ void tg_coldiff_kernel(const float* __restrict__ src,
                                  const float* __restrict__ tgt) {
    int d = threadIdx.x;
    int b = blockIdx.x;
    int r0 = b * (NPTS / 128);
    float s = 0.f;
    for (int r = 0; r < NPTS / 128; r++) {
        size_t idx = (size_t)(r0 + r) * DIM + d;
        s += src[idx] - tgt[idx];
    }
    g_colpart[b * DIM + d] = s;
}

// ---- main: fused cdist + row-sum + per-half top-11 ----
__global__ void __launch_bounds__(NTHREADS, 1)
tg_main_kernel(const float* __restrict__ X)
{
    extern __shared__ float sm[];
    float* As     = sm;                          // [256][132]
    float* Bs     = As + DIM * PITCH_A;          // [2][KB][128]
    float* sqA    = Bs + 2 * KB * TN;            // 128
    float* sqC    = sqA + TM;                    // 128
    float* heap   = sqC + TN;                    // 128*12
    float* rowmax = heap + TM * 12;              // 128
    float* red    = rowmax + TM;                 // 128*16
    int*   locks  = (int*)(red + TM * 16);       // 128

    const int tid  = threadIdx.x;
    const int lane = tid & 31;
    const int warp = tid >> 5;
    const int warp_r = warp >> 1;       // 0..7
    const int warp_c = warp & 1;        // 0..1
    const int lane_r = lane >> 3;       // 0..3
    const int lane_c = lane & 7;        // 0..7
    const int arow = warp_r * 16 + lane_r * 4;   // 4 rows
    const int bcol = warp_c * 64 + lane_c * 4;   // cols bcol..+3, +32..+35

    const int rt = blockIdx.x >> 1;
    const int h  = blockIdx.x & 1;
    const int rowbase = rt * TM;
    const int colhalf = h * HALF;

    for (int i = tid; i < TM * 12; i += NTHREADS) heap[i] = BIGF;
    if (tid < TM) {
        rowmax[tid] = BIGF;
        locks[tid]  = 0;
        sqA[tid]    = g_sq[rowbase + tid];
    }

    // A tile -> smem transposed, pitch 132 (row-fast mapping, conflict-free STS)
    #pragma unroll
    for (int i = 0; i < 16; i++) {
        int li = tid + i * NTHREADS;   // 0..8191 (r, kq) units
        int r  = li & 127;
        int kq = li >> 7;              // 0..63
        float4 v = *(const float4*)(X + (size_t)(rowbase + r) * DIM + kq * 4);
        int k0 = kq * 4;
        As[(k0 + 0) * PITCH_A + r] = v.x;
        As[(k0 + 1) * PITCH_A + r] = v.y;
        As[(k0 + 2) * PITCH_A + r] = v.z;
        As[(k0 + 3) * PITCH_A + r] = v.w;
    }
    __syncthreads();

    const int scol = tid & 127;        // staging: column
    const int skq  = tid >> 7;         // 0..3 (float4 slot within 16-k chunk)

    float rsum[4] = {0.f, 0.f, 0.f, 0.f};

    for (int ct = 0; ct < NCT; ct++) {
        const int colbase = colhalf + ct * TN;
        __syncthreads();               // prior epilogue done (sqC, Bs reuse)
        if (tid < TN) sqC[tid] = g_sq[colbase + tid];

        const float* Bg = X + (size_t)colbase * DIM;

        // stage chunk 0 -> buffer 0
        {
            float4 v = *(const float4*)(Bg + scol * DIM + skq * 4);
            int k0 = skq * 4;
            Bs[(k0 + 0) * TN + scol] = v.x;
            Bs[(k0 + 1) * TN + scol] = v.y;
            Bs[(k0 + 2) * TN + scol] = v.z;
            Bs[(k0 + 3) * TN + scol] = v.w;
        }
        __syncthreads();

        u64 acc[4][4];
        #pragma unroll
        for (int i = 0; i < 4; i++)
            #pragma unroll
            for (int j = 0; j < 4; j++) acc[i][j] = 0ull;

        for (int kc = 0; kc < NKC; kc++) {
            float4 bnext;
            if (kc + 1 < NKC)
                bnext = *(const float4*)(Bg + scol * DIM + (kc + 1) * KB + skq * 4);

            const float* Bsb = Bs + (kc & 1) * (KB * TN);
            const int kabs0 = kc * KB;
            #pragma unroll
            for (int kk = 0; kk < KB; kk++) {
                float4 a  = *(const float4*)(As + (kabs0 + kk) * PITCH_A + arow);
                float4 b0 = *(const float4*)(Bsb + kk * TN + bcol);
                float4 b1 = *(const float4*)(Bsb + kk * TN + bcol + 32);
                u64 ap0 = pack2(a.x, a.x), ap1 = pack2(a.y, a.y);
                u64 ap2 = pack2(a.z, a.z), ap3 = pack2(a.w, a.w);
                u64 bp0 = pack2(b0.x, b0.y), bp1 = pack2(b0.z, b0.w);
                u64 bp2 = pack2(b1.x, b1.y), bp3 = pack2(b1.z, b1.w);
                ffma2(acc[0][0], ap0, bp0); ffma2(acc[0][1], ap0, bp1);
                ffma2(acc[0][2], ap0, bp2); ffma2(acc[0][3], ap0, bp3);
                ffma2(acc[1][0], ap1, bp0); ffma2(acc[1][1], ap1, bp1);
                ffma2(acc[1][2], ap1, bp2); ffma2(acc[1][3], ap1, bp3);
                ffma2(acc[2][0], ap2, bp0); ffma2(acc[2][1], ap2, bp1);
                ffma2(acc[2][2], ap2, bp2); ffma2(acc[2][3], ap2, bp3);
                ffma2(acc[3][0], ap3, bp0); ffma2(acc[3][1], ap3, bp1);
                ffma2(acc[3][2], ap3, bp2); ffma2(acc[3][3], ap3, bp3);
            }
            __syncthreads();
            if (kc + 1 < NKC) {
                float* Bsn = Bs + ((kc + 1) & 1) * (KB * TN);
                int k0 = skq * 4;
                Bsn[(k0 + 0) * TN + scol] = bnext.x;
                Bsn[(k0 + 1) * TN + scol] = bnext.y;
                Bsn[(k0 + 2) * TN + scol] = bnext.z;
                Bsn[(k0 + 3) * TN + scol] = bnext.w;
                __syncthreads();
            }
        }

        // epilogue: d2 -> dist -> row sums + top-11
        #pragma unroll
        for (int i = 0; i < 4; i++) {
            int r = arow + i;
            float sa = sqA[r];
            float rs = 0.f;
            #pragma unroll
            for (int j = 0; j < 4; j++) {
                int c0 = bcol + (j >> 1) * 32 + (j & 1) * 2;
                float lo, hi; unpack2(acc[i][j], lo, hi);
                float d2a = fmaxf(sa + sqC[c0]     - 2.f * lo, 0.f);
                float d2b = fmaxf(sa + sqC[c0 + 1] - 2.f * hi, 0.f);
                float da = d2a * rsqrtf(fmaxf(d2a, 1e-12f));
                float db = d2b * rsqrtf(fmaxf(d2b, 1e-12f));
                rs += da + db;
                if (da < ((volatile float*)rowmax)[r])
                    topk_insert(heap, rowmax, locks, r, da);
                if (db < ((volatile float*)rowmax)[r])
                    topk_insert(heap, rowmax, locks, r, db);
            }
            rsum[i] += rs;
        }
    }

    // deterministic row-sum reduction (16 threads per row)
    __syncthreads();
    const int slot = warp_c * 8 + lane_c;
    #pragma unroll
    for (int i = 0; i < 4; i++) red[(arow + i) * 16 + slot] = rsum[i];
    __syncthreads();
    if (tid < TM) {
        float s = 0.f;
        #pragma unroll
        for (int t = 0; t < 16; t++) s += red[tid * 16 + t];
        int gr = rowbase + tid;
        g_psum[h * NPTS + gr] = s;
        #pragma unroll
        for (int t = 0; t < KNN; t++)
            g_ptopk[(size_t)(h * NPTS + gr) * 12 + t] = heap[tid * 12 + t];
    }
}

// ---- merge halves, TSDM head, per-block disc sums ----
__global__ void tg_merge_kernel(const float* __restrict__ w_tsdm,
                                const float* __restrict__ b_tsdm)
{
    __shared__ float buf[256];
    int r = blockIdx.x * 256 + threadIdx.x;
    float cand[2 * KNN];
    #pragma unroll
    for (int t = 0; t < KNN; t++) {
        cand[t]       = g_ptopk[(size_t)r * 12 + t];
        cand[KNN + t] = g_ptopk[(size_t)(NPTS + r) * 12 + t];
    }
    float sep = (g_psum[r] + g_psum[NPTS + r]) * (1.f / (float)(NPTS - 1));
    float s11 = 0.f, mn = 0.f;
    for (int t = 0; t < KNN; t++) {
        int mi = 0; float mv = cand[0];
        #pragma unroll
        for (int u = 1; u < 2 * KNN; u++)
            if (cand[u] < mv) { mv = cand[u]; mi = u; }
        s11 += mv;
        if (t == 0) mn = mv;
        cand[mi] = BIGF;
    }
    float comp = (s11 - mn) * 0.1f;
    float disc = fabsf(comp * w_tsdm[0] + sep * w_tsdm[1] + b_tsdm[0]);
    buf[threadIdx.x] = disc;
    __syncthreads();
    if (threadIdx.x == 0) {
        float s = 0.f;
        for (int i = 0; i < 256; i++) s += buf[i];
        g_disc[blockIdx.x] = s;
    }
}

// ---- final: GDDM head + disc mean ----
__global__ void tg_final_kernel(const float* __restrict__ w_gddm,
                                const float* __restrict__ b_gddm,
                                float* __restrict__ out)
{
    __shared__ float buf[DIM];
    int d = threadIdx.x;
    float s = 0.f;
    for (int b = 0; b < 128; b++) s += g_colpart[b * DIM + d];
    buf[d] = (s * (1.f / (float)NPTS)) * w_gddm[d];
    __syncthreads();
    if (d == 0) {
        float t = 0.f;
        for (int i = 0; i < DIM; i++) t += buf[i];
        out[0] = fabsf(t + b_gddm[0]);        // loss_gdd
        float ds = 0.f;
        for (int i = 0; i < 32; i++) ds += g_disc[i];
        out[1] = ds * (1.f / (float)NPTS);    // disc_loss
    }
}

extern "C" void kernel_launch(void* const* d_in, const int* in_sizes, int n_in,
                              void* d_out, int out_size) {
    const float* src    = (const float*)d_in[0];
    const float* tgt    = (const float*)d_in[1];
    const float* w_tsdm = (const float*)d_in[2];
    const float* b_tsdm = (const float*)d_in[3];
    const float* w_gddm = (const float*)d_in[4];
    const float* b_gddm = (const float*)d_in[5];
    float* out = (float*)d_out;

    size_t smem_bytes = (size_t)(DIM * PITCH_A + 2 * KB * TN + TM + TN +
                                 TM * 12 + TM + TM * 16 + TM) * sizeof(float);
    cudaFuncSetAttribute(tg_main_kernel,
                         cudaFuncAttributeMaxDynamicSharedMemorySize,
                         (int)smem_bytes);

    tg_sq_kernel<<<NPTS / 8, 256>>>(tgt);
    tg_coldiff_kernel<<<128, DIM>>>(src, tgt);
    tg_main_kernel<<<128, NTHREADS, smem_bytes>>>(tgt);
    tg_merge_kernel<<<32, 256>>>(w_tsdm, b_tsdm);
    tg_final_kernel<<<1, DIM>>>(w_gddm, b_gddm, out);
}

// round 5
// speedup vs baseline: 5.5632x; 3.5797x over previous
#include <cuda_runtime.h>
#include <cstdint>

#define NPTS 8192
#define DIM  256
#define KNN  11
#define TM   128
#define TN   128
#define HALF 4096
#define NCT  32            // col tiles per CTA
#define KC   64            // k per chunk
#define NKC  4
#define NTHREADS 512
#define PA   260           // A smem pitch (floats); 260%32=4 -> conflict-free frags
#define PB   68            // B smem pitch (floats); 68%32=4
#define BIGF 1e30f

// smem float offsets
#define OF_A   0
#define OF_B   (128 * PA)                  // 33280
#define OF_SQC (OF_B + 2 * 128 * PB)       // + 17408
#define OF_RS  (OF_SQC + 128)
#define SM_FLOATS (OF_RS + 512)            // 51328 floats = 205312 B

__device__ float g_sq[NPTS];
__device__ float g_colpart[128 * DIM];
__device__ float g_psum[2 * NPTS];
__device__ float g_ptopk[(size_t)2 * NPTS * 16 * 12];
__device__ float g_disc[64];

__device__ __forceinline__ uint32_t smem_u32(const void* p) {
    uint32_t a;
    asm("{ .reg .u64 t; cvta.to.shared.u64 t, %1; cvt.u32.u64 %0, t; }"
        : "=r"(a) : "l"(p));
    return a;
}
__device__ __forceinline__ void cpasync16(uint32_t dst, const void* src) {
    asm volatile("cp.async.cg.shared.global [%0], [%1], 16;"
                 :: "r"(dst), "l"(src) : "memory");
}
#define CP_COMMIT() asm volatile("cp.async.commit_group;" ::: "memory")
#define CP_WAIT(n)  asm volatile("cp.async.wait_group %0;" :: "n"(n) : "memory")

__device__ __forceinline__ void mma_tf32(float* d, const uint32_t* a,
                                         const uint32_t* b) {
    asm volatile(
        "mma.sync.aligned.m16n8k8.row.col.f32.tf32.tf32.f32 "
        "{%0,%1,%2,%3}, {%4,%5,%6,%7}, {%8,%9}, {%0,%1,%2,%3};"
        : "+f"(d[0]), "+f"(d[1]), "+f"(d[2]), "+f"(d[3])
        : "r"(a[0]), "r"(a[1]), "r"(a[2]), "r"(a[3]), "r"(b[0]), "r"(b[1]));
}

// FFMA-pipe sqrt (input >= 1e-12), rel err ~5e-6
__device__ __forceinline__ float fsqrt_nr(float x) {
    float xh = 0.5f * x;
    int i = 0x5f3759df - (__float_as_int(x) >> 1);
    float y = __int_as_float(i);
    y = y * (1.5f - xh * y * y);
    y = y * (1.5f - xh * y * y);
    return x * y;
}

// insert d into ascending sorted 11-array (caller checked d < hh[10])
__device__ __forceinline__ void ins11(float* hh, float d) {
    hh[10] = d;
    #pragma unroll
    for (int t = 10; t > 0; t--) {
        float lo = fminf(hh[t - 1], hh[t]);
        float hi = fmaxf(hh[t - 1], hh[t]);
        hh[t - 1] = lo; hh[t] = hi;
    }
}

// ---- aux: row squared norms ----
__global__ void tg_sq_kernel(const float* __restrict__ x) {
    int warp = (blockIdx.x * blockDim.x + threadIdx.x) >> 5;
    int lane = threadIdx.x & 31;
    const float* row = x + (size_t)warp * DIM;
    float s = 0.f;
    #pragma unroll
    for (int i = 0; i < DIM / 32; i++) {
        float v = row[lane + i * 32];
        s = fmaf(v, v, s);
    }
    #pragma unroll
    for (int o = 16; o; o >>= 1) s += __shfl_xor_sync(0xffffffffu, s, o);
    if (lane == 0) g_sq[warp] = s;
}

// ---- aux: GDDM column sums ----
__global__ void tg_coldiff_kernel(const float* __restrict__ src,
                                  const float* __restrict__ tgt) {
    int d = threadIdx.x;
    int b = blockIdx.x;
    int r0 = b * (NPTS / 128);
    float s = 0.f;
    for (int r = 0; r < NPTS / 128; r++) {
        size_t idx = (size_t)(r0 + r) * DIM + d;
        s += src[idx] - tgt[idx];
    }
    g_colpart[b * DIM + d] = s;
}

// ---- main: tf32 mma.sync Gram + fused distance epilogue ----
__global__ void __launch_bounds__(NTHREADS, 1)
tg_main_kernel(const float* __restrict__ X)
{
    extern __shared__ float sm[];
    float* As    = sm + OF_A;
    float* Bs    = sm + OF_B;
    float* sqC   = sm + OF_SQC;
    float* rsbuf = sm + OF_RS;
    const uint32_t sb_A = smem_u32(As);
    const uint32_t sb_B = smem_u32(Bs);

    const int tid  = threadIdx.x;
    const int lane = tid & 31;
    const int warp = tid >> 5;
    const int wr   = warp >> 2;          // 0..3 row group (32 rows)
    const int wc   = warp & 3;           // 0..3 col group (32 cols)
    const int qid  = lane >> 2;          // 0..7
    const int qt   = lane & 3;           // 0..3
    const int rt   = blockIdx.x >> 1;
    const int h    = blockIdx.x & 1;
    const int rowbase = rt * TM;
    const int colhalf = h * HALF;

    // stage A tile via cp.async: 128 rows x 256 floats, pitch PA
    #pragma unroll
    for (int i = 0; i < 16; i++) {
        int idx = tid + i * NTHREADS;     // 0..8191 float4s
        int r = idx >> 6, f4 = idx & 63;
        cpasync16(sb_A + (uint32_t)(r * PA + f4 * 4) * 4,
                  X + (size_t)(rowbase + r) * DIM + f4 * 4);
    }
    CP_COMMIT();

    float sa[4];
    #pragma unroll
    for (int s = 0; s < 4; s++)
        sa[s] = g_sq[rowbase + wr * 32 + qid + s * 8];

    float hreg[4][11];
    #pragma unroll
    for (int s = 0; s < 4; s++)
        #pragma unroll
        for (int t = 0; t < KNN; t++) hreg[s][t] = BIGF;
    float rowsum[4] = {0.f, 0.f, 0.f, 0.f};

    CP_WAIT(0);
    __syncthreads();

    const uint32_t* Au = (const uint32_t*)As;

    for (int ct = 0; ct < NCT; ct++) {
        const int colbase = colhalf + ct * TN;
        __syncthreads();                 // prev epilogue / compute done
        if (tid < 128) sqC[tid] = g_sq[colbase + tid];

        // stage chunk 0 -> buf 0
        #pragma unroll
        for (int p = 0; p < 4; p++) {
            int idx = tid + p * NTHREADS;   // 0..2047 float4s
            int r = idx >> 4, f4 = idx & 15;
            cpasync16(sb_B + (uint32_t)(r * PB + f4 * 4) * 4,
                      X + (size_t)(colbase + r) * DIM + f4 * 4);
        }
        CP_COMMIT();

        float acc[2][4][4];
        #pragma unroll
        for (int mi = 0; mi < 2; mi++)
            #pragma unroll
            for (int ni = 0; ni < 4; ni++)
                #pragma unroll
                for (int j = 0; j < 4; j++) acc[mi][ni][j] = 0.f;

        for (int kc = 0; kc < NKC; kc++) {
            if (kc + 1 < NKC) {
                uint32_t bofs = ((kc + 1) & 1) * (128 * PB * 4);
                #pragma unroll
                for (int p = 0; p < 4; p++) {
                    int idx = tid + p * NTHREADS;
                    int r = idx >> 4, f4 = idx & 15;
                    cpasync16(sb_B + bofs + (uint32_t)(r * PB + f4 * 4) * 4,
                              X + (size_t)(colbase + r) * DIM + (kc + 1) * KC + f4 * 4);
                }
                CP_COMMIT();
                CP_WAIT(1);
            } else {
                CP_WAIT(0);
            }
            __syncthreads();

            const uint32_t* Bu = (const uint32_t*)(Bs + (kc & 1) * (128 * PB));
            const int kb = kc * KC;
            #pragma unroll
            for (int kk = 0; kk < 8; kk++) {
                const int kg = kb + kk * 8 + qt;
                uint32_t af[2][4], bf[4][2];
                #pragma unroll
                for (int mi = 0; mi < 2; mi++) {
                    int ro = (wr * 32 + mi * 16 + qid) * PA + kg;
                    af[mi][0] = Au[ro];
                    af[mi][1] = Au[ro + 8 * PA];
                    af[mi][2] = Au[ro + 4];
                    af[mi][3] = Au[ro + 8 * PA + 4];
                }
                #pragma unroll
                for (int ni = 0; ni < 4; ni++) {
                    int co = (wc * 32 + ni * 8 + qid) * PB + kk * 8 + qt;
                    bf[ni][0] = Bu[co];
                    bf[ni][1] = Bu[co + 4];
                }
                #pragma unroll
                for (int mi = 0; mi < 2; mi++)
                    #pragma unroll
                    for (int ni = 0; ni < 4; ni++)
                        mma_tf32(acc[mi][ni], af[mi], bf[ni]);
            }
            __syncthreads();             // readers done before next stage
        }

        // epilogue: distances, row sums, reg top-11
        #pragma unroll
        for (int mi = 0; mi < 2; mi++)
            #pragma unroll
            for (int hf = 0; hf < 2; hf++) {
                const int s = mi * 2 + hf;
                #pragma unroll
                for (int ni = 0; ni < 4; ni++)
                    #pragma unroll
                    for (int c = 0; c < 2; c++) {
                        float dot = acc[mi][ni][hf * 2 + c];
                        int col = wc * 32 + ni * 8 + qt * 2 + c;
                        float d2 = fmaxf(fmaf(dot, -2.f, sa[s] + sqC[col]), 1e-12f);
                        float dst = fsqrt_nr(d2);
                        rowsum[s] += dst;
                        if (dst < hreg[s][10]) ins11(hreg[s], dst);
                    }
            }
    }

    // row-sum: quad reduce then 4-wc merge via smem
    #pragma unroll
    for (int s = 0; s < 4; s++) {
        rowsum[s] += __shfl_xor_sync(0xffffffffu, rowsum[s], 1);
        rowsum[s] += __shfl_xor_sync(0xffffffffu, rowsum[s], 2);
    }
    __syncthreads();
    if (qt == 0) {
        #pragma unroll
        for (int s = 0; s < 4; s++)
            rsbuf[(wr * 32 + qid + s * 8) * 4 + wc] = rowsum[s];
    }
    __syncthreads();
    if (tid < 128) {
        float sum = rsbuf[tid * 4] + rsbuf[tid * 4 + 1] +
                    rsbuf[tid * 4 + 2] + rsbuf[tid * 4 + 3];
        g_psum[h * NPTS + rowbase + tid] = sum;
    }

    // dump per-(thread,slot) top-11: 16 sets per row
    #pragma unroll
    for (int s = 0; s < 4; s++) {
        int row = wr * 32 + qid + s * 8;
        int set = wc * 4 + qt;
        size_t base = ((size_t)(h * NPTS + rowbase + row) * 16 + set) * 12;
        #pragma unroll
        for (int t = 0; t < KNN; t++) g_ptopk[base + t] = hreg[s][t];
    }
}

// ---- merge: 32 candidate sets per row -> TSDM head ----
__global__ void tg_merge_kernel(const float* __restrict__ w_tsdm,
                                const float* __restrict__ b_tsdm)
{
    __shared__ float buf[128];
    int row = blockIdx.x * 128 + threadIdx.x;
    float hh[11];
    #pragma unroll
    for (int t = 0; t < KNN; t++) hh[t] = BIGF;
    for (int half = 0; half < 2; half++) {
        size_t rb = (size_t)(half * NPTS + row) * 16;
        for (int set = 0; set < 16; set++) {
            size_t base = (rb + set) * 12;
            for (int t = 0; t < KNN; t++) {
                float d = g_ptopk[base + t];
                if (d < hh[10]) ins11(hh, d);
            }
        }
    }
    float sep = (g_psum[row] + g_psum[NPTS + row]) * (1.f / (float)(NPTS - 1));
    float s11 = 0.f;
    #pragma unroll
    for (int t = 0; t < KNN; t++) s11 += hh[t];
    float comp = (s11 - hh[0]) * 0.1f;
    float disc = fabsf(comp * w_tsdm[0] + sep * w_tsdm[1] + b_tsdm[0]);
    buf[threadIdx.x] = disc;
    __syncthreads();
    if (threadIdx.x == 0) {
        float s = 0.f;
        for (int i = 0; i < 128; i++) s += buf[i];
        g_disc[blockIdx.x] = s;
    }
}

// ---- final: GDDM head + disc mean ----
__global__ void tg_final_kernel(const float* __restrict__ w_gddm,
                                const float* __restrict__ b_gddm,
                                float* __restrict__ out)
{
    __shared__ float buf[DIM];
    int d = threadIdx.x;
    float s = 0.f;
    for (int b = 0; b < 128; b++) s += g_colpart[b * DIM + d];
    buf[d] = (s * (1.f / (float)NPTS)) * w_gddm[d];
    __syncthreads();
    if (d == 0) {
        float t = 0.f;
        for (int i = 0; i < DIM; i++) t += buf[i];
        out[0] = fabsf(t + b_gddm[0]);
        float ds = 0.f;
        for (int i = 0; i < 64; i++) ds += g_disc[i];
        out[1] = ds * (1.f / (float)NPTS);
    }
}

extern "C" void kernel_launch(void* const* d_in, const int* in_sizes, int n_in,
                              void* d_out, int out_size) {
    const float* src    = (const float*)d_in[0];
    const float* tgt    = (const float*)d_in[1];
    const float* w_tsdm = (const float*)d_in[2];
    const float* b_tsdm = (const float*)d_in[3];
    const float* w_gddm = (const float*)d_in[4];
    const float* b_gddm = (const float*)d_in[5];
    float* out = (float*)d_out;

    cudaFuncSetAttribute(tg_main_kernel,
                         cudaFuncAttributeMaxDynamicSharedMemorySize,
                         SM_FLOATS * 4);

    tg_sq_kernel<<<NPTS / 8, 256>>>(tgt);
    tg_coldiff_kernel<<<128, DIM>>>(src, tgt);
    tg_main_kernel<<<128, NTHREADS, SM_FLOATS * 4>>>(tgt);
    tg_merge_kernel<<<NPTS / 128, 128>>>(w_tsdm, b_tsdm);
    tg_final_kernel<<<1, DIM>>>(w_gddm, b_gddm, out);
}

// round 6
// speedup vs baseline: 8.6115x; 1.5479x over previous
#include <cuda_runtime.h>
#include <cuda_bf16.h>
#include <cstdint>

#define NPTS 8192
#define DIM  256
#define KNN  11
#define TM   128
#define TN   128
#define HALF 4096
#define NCT  32            // col tiles per CTA
#define NTHREADS 512
#define PAH  264           // smem pitch in halves (528 B row, 132 words, %32=4)
#define BIGF 1e30f

// smem byte offsets
#define SMB_A   0
#define TILE_B  (128 * PAH * 2)        // 67584 bytes per tile buffer
#define SMB_B   TILE_B                 // two B buffers follow A
#define SMB_RS  (TILE_B * 3)           // 202752
#define SM_TOTAL (SMB_RS + 2048)       // 204800 B

__device__ __align__(16) __nv_bfloat16 g_xbf[(size_t)NPTS * DIM];
__device__ float g_sq[NPTS];
__device__ float g_colpart[128 * DIM];
__device__ float g_psum[2 * NPTS];
__device__ float g_ptopk[(size_t)2 * NPTS * 12];
__device__ float g_disc[64];

__device__ __forceinline__ uint32_t smem_u32(const void* p) {
    uint32_t a;
    asm("{ .reg .u64 t; cvta.to.shared.u64 t, %1; cvt.u32.u64 %0, t; }"
        : "=r"(a) : "l"(p));
    return a;
}
__device__ __forceinline__ void cpasync16(uint32_t dst, const void* src) {
    asm volatile("cp.async.cg.shared.global [%0], [%1], 16;"
                 :: "r"(dst), "l"(src) : "memory");
}
#define CP_COMMIT() asm volatile("cp.async.commit_group;" ::: "memory")
#define CP_WAIT0()  asm volatile("cp.async.wait_group 0;" ::: "memory")

__device__ __forceinline__ void mma_bf16(float* d, const uint32_t* a,
                                         const uint32_t* b) {
    asm volatile(
        "mma.sync.aligned.m16n8k16.row.col.f32.bf16.bf16.f32 "
        "{%0,%1,%2,%3}, {%4,%5,%6,%7}, {%8,%9}, {%0,%1,%2,%3};"
        : "+f"(d[0]), "+f"(d[1]), "+f"(d[2]), "+f"(d[3])
        : "r"(a[0]), "r"(a[1]), "r"(a[2]), "r"(a[3]), "r"(b[0]), "r"(b[1]));
}

// FFMA-pipe sqrt (input >= 1e-12), rel err ~5e-6
__device__ __forceinline__ float fsqrt_nr(float x) {
    float xh = 0.5f * x;
    int i = 0x5f3759df - (__float_as_int(x) >> 1);
    float y = __int_as_float(i);
    y = y * (1.5f - xh * y * y);
    y = y * (1.5f - xh * y * y);
    return x * y;
}

// insert d into ascending sorted 11-array (caller checked d < hh[10])
__device__ __forceinline__ void ins11(float* hh, float d) {
    hh[10] = d;
    #pragma unroll
    for (int t = 10; t > 0; t--) {
        float lo = fminf(hh[t - 1], hh[t]);
        float hi = fmaxf(hh[t - 1], hh[t]);
        hh[t - 1] = lo; hh[t] = hi;
    }
}

// ---- convert X to bf16 ----
__global__ void tg_convert_kernel(const float* __restrict__ x) {
    int i = (blockIdx.x * blockDim.x + threadIdx.x) * 4;
    float4 v = *(const float4*)(x + i);
    __nv_bfloat162* o = (__nv_bfloat162*)(g_xbf + i);
    o[0] = __floats2bfloat162_rn(v.x, v.y);
    o[1] = __floats2bfloat162_rn(v.z, v.w);
}

// ---- row squared norms (fp32) ----
__global__ void tg_sq_kernel(const float* __restrict__ x) {
    int warp = (blockIdx.x * blockDim.x + threadIdx.x) >> 5;
    int lane = threadIdx.x & 31;
    const float* row = x + (size_t)warp * DIM;
    float s = 0.f;
    #pragma unroll
    for (int i = 0; i < DIM / 32; i++) {
        float v = row[lane + i * 32];
        s = fmaf(v, v, s);
    }
    #pragma unroll
    for (int o = 16; o; o >>= 1) s += __shfl_xor_sync(0xffffffffu, s, o);
    if (lane == 0) g_sq[warp] = s;
}

// ---- GDDM column sums ----
__global__ void tg_coldiff_kernel(const float* __restrict__ src,
                                  const float* __restrict__ tgt) {
    int d = threadIdx.x;
    int b = blockIdx.x;
    int r0 = b * (NPTS / 128);
    float s = 0.f;
    for (int r = 0; r < NPTS / 128; r++) {
        size_t idx = (size_t)(r0 + r) * DIM + d;
        s += src[idx] - tgt[idx];
    }
    g_colpart[b * DIM + d] = s;
}

// ---- main: bf16 mma.sync Gram + fused distance epilogue ----
__global__ void __launch_bounds__(NTHREADS, 1)
tg_main_kernel()
{
    extern __shared__ char sm[];
    const uint32_t smb = smem_u32(sm);
    const __nv_bfloat16* As = (const __nv_bfloat16*)sm;
    float* rsbuf = (float*)(sm + SMB_RS);

    const int tid  = threadIdx.x;
    const int lane = tid & 31;
    const int warp = tid >> 5;
    const int wr   = warp >> 2;          // 0..3: 32-row group
    const int wc   = warp & 3;           // 0..3: 32-col group
    const int qid  = lane >> 2;          // 0..7
    const int qt   = lane & 3;           // 0..3
    const int rt   = blockIdx.x >> 1;
    const int h    = blockIdx.x & 1;
    const int rowbase = rt * TM;
    const int colhalf = h * HALF;

    const int sr = tid >> 5;             // staging row base helper (unused名)
    (void)sr;

    // stage A tile + B tile 0
    {
        const __nv_bfloat16* Ag = g_xbf + (size_t)rowbase * DIM;
        const __nv_bfloat16* Bg = g_xbf + (size_t)colhalf * DIM;
        #pragma unroll
        for (int p = 0; p < 8; p++) {
            int idx = tid + p * NTHREADS;    // 0..4095
            int r = idx >> 5, f = idx & 31;
            cpasync16(smb + SMB_A + r * (PAH * 2) + f * 16, Ag + r * DIM + f * 8);
            cpasync16(smb + SMB_B + r * (PAH * 2) + f * 16, Bg + r * DIM + f * 8);
        }
        CP_COMMIT();
    }

    float sa[4];
    #pragma unroll
    for (int s = 0; s < 4; s++)
        sa[s] = g_sq[rowbase + wr * 32 + qid + s * 8];

    float hreg[4][11];
    #pragma unroll
    for (int s = 0; s < 4; s++)
        #pragma unroll
        for (int t = 0; t < KNN; t++) hreg[s][t] = BIGF;
    float rowsum[4] = {0.f, 0.f, 0.f, 0.f};

    CP_WAIT0();
    __syncthreads();

    for (int ct = 0; ct < NCT; ct++) {
        // prefetch next B tile into the other buffer
        if (ct + 1 < NCT) {
            const __nv_bfloat16* Bg = g_xbf +
                (size_t)(colhalf + (ct + 1) * TN) * DIM;
            uint32_t dst = smb + SMB_B + ((ct + 1) & 1) * TILE_B;
            #pragma unroll
            for (int p = 0; p < 8; p++) {
                int idx = tid + p * NTHREADS;
                int r = idx >> 5, f = idx & 31;
                cpasync16(dst + r * (PAH * 2) + f * 16, Bg + r * DIM + f * 8);
            }
            CP_COMMIT();
        }

        const __nv_bfloat16* Bs =
            (const __nv_bfloat16*)(sm + SMB_B + (ct & 1) * TILE_B);

        float acc[2][4][4];
        #pragma unroll
        for (int mi = 0; mi < 2; mi++)
            #pragma unroll
            for (int ni = 0; ni < 4; ni++)
                #pragma unroll
                for (int j = 0; j < 4; j++) acc[mi][ni][j] = 0.f;

        #pragma unroll 4
        for (int kk = 0; kk < 16; kk++) {
            const int kb = kk * 16 + 2 * qt;
            uint32_t af[2][4], bfr[4][2];
            #pragma unroll
            for (int mi = 0; mi < 2; mi++) {
                const __nv_bfloat16* ap =
                    As + (wr * 32 + mi * 16 + qid) * PAH + kb;
                af[mi][0] = *(const uint32_t*)(ap);
                af[mi][1] = *(const uint32_t*)(ap + 8 * PAH);
                af[mi][2] = *(const uint32_t*)(ap + 8);
                af[mi][3] = *(const uint32_t*)(ap + 8 * PAH + 8);
            }
            #pragma unroll
            for (int ni = 0; ni < 4; ni++) {
                const __nv_bfloat16* bp =
                    Bs + (wc * 32 + ni * 8 + qid) * PAH + kb;
                bfr[ni][0] = *(const uint32_t*)(bp);
                bfr[ni][1] = *(const uint32_t*)(bp + 8);
            }
            #pragma unroll
            for (int mi = 0; mi < 2; mi++)
                #pragma unroll
                for (int ni = 0; ni < 4; ni++)
                    mma_bf16(acc[mi][ni], af[mi], bfr[ni]);
        }

        // epilogue: distances, row sums, reg top-11
        const int colbase = colhalf + ct * TN;
        #pragma unroll
        for (int ni = 0; ni < 4; ni++)
            #pragma unroll
            for (int c = 0; c < 2; c++) {
                const int col = colbase + wc * 32 + ni * 8 + 2 * qt + c;
                const float sc = __ldg(&g_sq[col]);
                #pragma unroll
                for (int mi = 0; mi < 2; mi++)
                    #pragma unroll
                    for (int hf = 0; hf < 2; hf++) {
                        const int s = mi * 2 + hf;
                        float dot = acc[mi][ni][hf * 2 + c];
                        float d2 = fmaxf(fmaf(dot, -2.f, sa[s] + sc), 1e-12f);
                        float dst = fsqrt_nr(d2);
                        rowsum[s] += dst;
                        if (dst < hreg[s][10]) ins11(hreg[s], dst);
                    }
            }

        CP_WAIT0();
        __syncthreads();       // next B tile ready; all reads of cur buf done
    }

    // row-sum: quad shuffle reduce then 4-wc merge
    #pragma unroll
    for (int s = 0; s < 4; s++) {
        rowsum[s] += __shfl_xor_sync(0xffffffffu, rowsum[s], 1);
        rowsum[s] += __shfl_xor_sync(0xffffffffu, rowsum[s], 2);
    }
    if (qt == 0) {
        #pragma unroll
        for (int s = 0; s < 4; s++)
            rsbuf[(wr * 32 + qid + s * 8) * 4 + wc] = rowsum[s];
    }

    // dump per-thread top-11 sets into smem (A region reused)
    float* dump = (float*)sm;            // [128 rows][16 sets][11]
    #pragma unroll
    for (int s = 0; s < 4; s++) {
        int row = wr * 32 + qid + s * 8;
        int set = wc * 4 + qt;
        float* d = dump + (row * 16 + set) * 11;
        #pragma unroll
        for (int t = 0; t < KNN; t++) d[t] = hreg[s][t];
    }
    __syncthreads();

    // 128 threads: merge 16 sets per row -> global 11 + rowsum
    if (tid < TM) {
        const int row = tid;
        float hh[11];
        #pragma unroll
        for (int t = 0; t < KNN; t++) hh[t] = dump[(row * 16) * 11 + t];
        for (int set = 1; set < 16; set++) {
            const float* d = dump + (row * 16 + set) * 11;
            #pragma unroll
            for (int t = 0; t < KNN; t++) {
                float v = d[t];
                if (v < hh[10]) ins11(hh, v);
            }
        }
        int gr = rowbase + row;
        size_t base = (size_t)(h * NPTS + gr) * 12;
        #pragma unroll
        for (int t = 0; t < KNN; t++) g_ptopk[base + t] = hh[t];
        g_psum[h * NPTS + gr] = rsbuf[row * 4] + rsbuf[row * 4 + 1] +
                                rsbuf[row * 4 + 2] + rsbuf[row * 4 + 3];
    }
}

// ---- merge 2 halves per row + TSDM head ----
__global__ void tg_merge_kernel(const float* __restrict__ w_tsdm,
                                const float* __restrict__ b_tsdm)
{
    __shared__ float buf[128];
    int row = blockIdx.x * 128 + threadIdx.x;
    float hh[11];
    size_t b0 = (size_t)row * 12;
    size_t b1 = (size_t)(NPTS + row) * 12;
    #pragma unroll
    for (int t = 0; t < KNN; t++) hh[t] = g_ptopk[b0 + t];
    #pragma unroll
    for (int t = 0; t < KNN; t++) {
        float v = g_ptopk[b1 + t];
        if (v < hh[10]) ins11(hh, v);
    }
    float sep = (g_psum[row] + g_psum[NPTS + row]) * (1.f / (float)(NPTS - 1));
    float s11 = 0.f;
    #pragma unroll
    for (int t = 0; t < KNN; t++) s11 += hh[t];
    float comp = (s11 - hh[0]) * 0.1f;
    float disc = fabsf(comp * w_tsdm[0] + sep * w_tsdm[1] + b_tsdm[0]);
    buf[threadIdx.x] = disc;
    __syncthreads();
    if (threadIdx.x == 0) {
        float s = 0.f;
        for (int i = 0; i < 128; i++) s += buf[i];
        g_disc[blockIdx.x] = s;
    }
}

// ---- final: GDDM head + disc mean ----
__global__ void tg_final_kernel(const float* __restrict__ w_gddm,
                                const float* __restrict__ b_gddm,
                                float* __restrict__ out)
{
    __shared__ float buf[DIM];
    int d = threadIdx.x;
    float s = 0.f;
    for (int b = 0; b < 128; b++) s += g_colpart[b * DIM + d];
    buf[d] = (s * (1.f / (float)NPTS)) * w_gddm[d];
    __syncthreads();
    if (d == 0) {
        float t = 0.f;
        for (int i = 0; i < DIM; i++) t += buf[i];
        out[0] = fabsf(t + b_gddm[0]);
        float ds = 0.f;
        for (int i = 0; i < 64; i++) ds += g_disc[i];
        out[1] = ds * (1.f / (float)NPTS);
    }
}

extern "C" void kernel_launch(void* const* d_in, const int* in_sizes, int n_in,
                              void* d_out, int out_size) {
    const float* src    = (const float*)d_in[0];
    const float* tgt    = (const float*)d_in[1];
    const float* w_tsdm = (const float*)d_in[2];
    const float* b_tsdm = (const float*)d_in[3];
    const float* w_gddm = (const float*)d_in[4];
    const float* b_gddm = (const float*)d_in[5];
    float* out = (float*)d_out;

    cudaFuncSetAttribute(tg_main_kernel,
                         cudaFuncAttributeMaxDynamicSharedMemorySize, SM_TOTAL);

    tg_convert_kernel<<<NPTS * DIM / 4 / 256, 256>>>(tgt);
    tg_sq_kernel<<<NPTS / 8, 256>>>(tgt);
    tg_coldiff_kernel<<<128, DIM>>>(src, tgt);
    tg_main_kernel<<<128, NTHREADS, SM_TOTAL>>>();
    tg_merge_kernel<<<NPTS / 128, 128>>>(w_tsdm, b_tsdm);
    tg_final_kernel<<<1, DIM>>>(w_gddm, b_gddm, out);
}